// round 14
// baseline (speedup 1.0000x reference)
#include <cuda_runtime.h>
#include <cuda_bf16.h>
#include <math_constants.h>

// N=16384 rows, C=1000 classes, 9 matrices (outputs1..8 + mimic).
// Per row/matrix: margin = (x[target] == top1) ? top1 - top2 : 0
// out_threshold = softmax(margins / 2) per row -> d_out[1 + row*9 + m]
// max_preds = max over all elements of matrices 0..7 -> d_out[0]
//
// R12 design (92.7us: row-pair per iteration, stride mapping, __ldcs payload)
// + software-pipelined target chain: tg/tv for pair p+stride are loaded during
// pair p's iteration, so the dependent targets->x[target] chain (~1200 cyc)
// is off the critical path. Single-variable change vs R12.

#define C_DIM  1000
#define CHUNKS 250          // C_DIM / 4 float4 chunks per row
#define BLOCK  288          // 9 warps
#define NEG_INF (-CUDART_INF_F)
#define ENC_NEG_INF 0x007FFFFFu   // enc_f(-inf)

struct Ptrs { const float* p[9]; };

__device__ unsigned g_max_enc = ENC_NEG_INF;
__device__ unsigned g_done    = 0u;

__device__ __forceinline__ unsigned enc_f(float x) {
    unsigned u = __float_as_uint(x);
    return (u & 0x80000000u) ? ~u : (u | 0x80000000u);
}
__device__ __forceinline__ float dec_f(unsigned e) {
    return (e & 0x80000000u) ? __uint_as_float(e ^ 0x80000000u)
                             : __uint_as_float(~e);
}

// accumulate top-2 of a float4 into (t1, t2)
__device__ __forceinline__ void acc4(float4 v, float& t1, float& t2) {
    float hi1 = fmaxf(v.x, v.y), lo1 = fminf(v.x, v.y);
    float hi2 = fmaxf(v.z, v.w), lo2 = fminf(v.z, v.w);
    float m1 = fmaxf(hi1, hi2);
    float m2 = fmaxf(fminf(hi1, hi2), (hi1 >= hi2) ? lo1 : lo2);
    t2 = fmaxf(fminf(t1, m1), fmaxf(t2, m2));
    t1 = fmaxf(t1, m1);
}

// target index for a row; values < 1000 so int is enough
__device__ __forceinline__ int load_tgi(const unsigned* t32, int row,
                                        unsigned is32) {
    if (is32) return __ldg(&((const int*)t32)[row]);
    return (int)__ldg(&((const long long*)t32)[row]);
}

__global__ __launch_bounds__(BLOCK, 5)
void margin_softmax_kernel(Ptrs ptrs, const unsigned* __restrict__ t32,
                           float* __restrict__ out, int nrows) {
    const int t    = threadIdx.x;
    const int lane = t & 31;
    const int w    = t >> 5;          // warp index == matrix index 0..8

    __shared__ float s_margin[2][2][12]; // [buf][row-in-pair][warp], padded
    __shared__ float s_gm[8];

    // targets dtype detect, once: int64 values < 1000 => all odd words 0
    unsigned odd  = __ldg(&t32[2 * lane + 1]);
    unsigned is32 = __reduce_or_sync(0xFFFFFFFFu, odd);

    const float* base = ptrs.p[w];
    float gm = NEG_INF;               // per-warp running max (lane 0 authoritative)

    const int npairs = (nrows + 1) >> 1;
    const int stride = gridDim.x;

    // ---- prologue: prefetch tg/tv for the first pair ----
    float tv0 = NEG_INF, tv1 = NEG_INF;
    {
        int p0 = blockIdx.x;
        if (p0 < npairs) {
            int r0 = 2 * p0;
            int tg0 = load_tgi(t32, r0, is32);
            int tg1 = load_tgi(t32, r0 + 1, is32);
            tv0 = __ldg(&base[(size_t)r0 * C_DIM + tg0]);
            tv1 = __ldg(&base[(size_t)(r0 + 1) * C_DIM + tg1]);
        }
    }

    int it = 0;
    for (int p = blockIdx.x; p < npairs; p += stride, ++it) {
        const int row0 = 2 * p;
        const int row1 = row0 + 1;

        // issue next pair's target-index loads immediately (independent)
        const int p_next = p + stride;
        const bool has_next = (p_next < npairs);
        const int rn0 = has_next ? 2 * p_next : row0;   // clamped-safe
        int tgn0 = load_tgi(t32, rn0, is32);
        int tgn1 = load_tgi(t32, rn0 + 1, is32);

        const float* rowp0 = base + (size_t)row0 * C_DIM;
        const float* rowp1 = rowp0 + C_DIM;
        const float4* r0 = reinterpret_cast<const float4*>(rowp0);
        const float4* r1 = reinterpret_cast<const float4*>(rowp1);

        // wave A: both rows, chunks lane + {0,32,64,96} -> 8 loads in flight
        float4 a00 = __ldcs(&r0[lane]);
        float4 a01 = __ldcs(&r0[lane + 32]);
        float4 a02 = __ldcs(&r0[lane + 64]);
        float4 a03 = __ldcs(&r0[lane + 96]);
        float4 a10 = __ldcs(&r1[lane]);
        float4 a11 = __ldcs(&r1[lane + 32]);
        float4 a12 = __ldcs(&r1[lane + 64]);
        float4 a13 = __ldcs(&r1[lane + 96]);

        float t1a = NEG_INF, t2a = NEG_INF;   // row0 top-2
        float t1b = NEG_INF, t2b = NEG_INF;   // row1 top-2
        acc4(a00, t1a, t2a); acc4(a10, t1b, t2b);
        acc4(a01, t1a, t2a); acc4(a11, t1b, t2b);
        acc4(a02, t1a, t2a); acc4(a12, t1b, t2b);
        acc4(a03, t1a, t2a); acc4(a13, t1b, t2b);

        // wave B: both rows, chunks lane + {128,160,192,224} (last predicated)
        float4 nf = make_float4(NEG_INF, NEG_INF, NEG_INF, NEG_INF);
        float4 b00 = __ldcs(&r0[lane + 128]);
        float4 b01 = __ldcs(&r0[lane + 160]);
        float4 b02 = __ldcs(&r0[lane + 192]);
        float4 b03 = (lane + 224 < CHUNKS) ? __ldcs(&r0[lane + 224]) : nf;
        float4 b10 = __ldcs(&r1[lane + 128]);
        float4 b11 = __ldcs(&r1[lane + 160]);
        float4 b12 = __ldcs(&r1[lane + 192]);
        float4 b13 = (lane + 224 < CHUNKS) ? __ldcs(&r1[lane + 224]) : nf;

        // tg_next has had wave A's flight time to arrive: issue tv_next now,
        // a full reduce+softmax+next-wave ahead of its use.
        const float* rnp0 = base + (size_t)rn0 * C_DIM;
        float tvn0 = __ldg(&rnp0[tgn0]);
        float tvn1 = __ldg(&rnp0[C_DIM + tgn1]);

        acc4(b00, t1a, t2a); acc4(b10, t1b, t2b);
        acc4(b01, t1a, t2a); acc4(b11, t1b, t2b);
        acc4(b02, t1a, t2a); acc4(b12, t1b, t2b);
        acc4(b03, t1a, t2a); acc4(b13, t1b, t2b);

        // warp top-2 reduction, 4 streams in one loop
#pragma unroll
        for (int off = 16; off > 0; off >>= 1) {
            float o1a = __shfl_down_sync(0xFFFFFFFFu, t1a, off);
            float o2a = __shfl_down_sync(0xFFFFFFFFu, t2a, off);
            float o1b = __shfl_down_sync(0xFFFFFFFFu, t1b, off);
            float o2b = __shfl_down_sync(0xFFFFFFFFu, t2b, off);
            t2a = fmaxf(fminf(t1a, o1a), fmaxf(t2a, o2a));
            t1a = fmaxf(t1a, o1a);
            t2b = fmaxf(fminf(t1b, o1b), fmaxf(t2b, o2b));
            t1b = fmaxf(t1b, o1b);
        }
        if (lane == 0) {
            s_margin[it & 1][0][w] = (tv0 == t1a) ? (t1a - t2a) : 0.0f;
            s_margin[it & 1][1][w] = (tv1 == t1b) ? (t1b - t2b) : 0.0f;
            gm = fmaxf(gm, fmaxf(t1a, t1b));    // row max == top1
        }
        __syncthreads();

        if (w == 0) {
            // two softmaxes in one warp: lanes 0..8 -> row0, 16..24 -> row1
            int half = lane >> 4;      // 0 or 1
            int l16  = lane & 15;
            float m = (l16 < 9) ? s_margin[it & 1][half][l16] : NEG_INF;
            float mm = m;
#pragma unroll
            for (int off = 8; off > 0; off >>= 1)
                mm = fmaxf(mm, __shfl_xor_sync(0xFFFFFFFFu, mm, off, 16));
            float e = __expf((m - mm) * 0.5f);
            float sum = e;
#pragma unroll
            for (int off = 8; off > 0; off >>= 1)
                sum += __shfl_xor_sync(0xFFFFFFFFu, sum, off, 16);
            int row = row0 + half;
            if (l16 < 9 && row < nrows)
                out[1 + (size_t)row * 9 + l16] = __fdividef(e, sum);
        }

        // rotate pipelined target values
        tv0 = tvn0;
        tv1 = tvn1;
        // s_margin WAR across iterations protected by double buffering.
    }

    // block-level scalar max: one shared write per warp, one atomic per block
    if (lane == 0 && w < 8) s_gm[w] = gm;
    __syncthreads();
    if (t == 0) {
        float g = s_gm[0];
#pragma unroll
        for (int i = 1; i < 8; i++) g = fmaxf(g, s_gm[i]);
        atomicMax(&g_max_enc, enc_f(g));
        __threadfence();
        unsigned done = atomicAdd(&g_done, 1u);
        if (done == gridDim.x - 1) {
            __threadfence();
            unsigned cur = atomicOr(&g_max_enc, 0u);   // atomic read
            out[0] = dec_f(cur);
            // reset scratch for next graph replay
            g_max_enc = ENC_NEG_INF;
            g_done    = 0u;
        }
    }
}

extern "C" void kernel_launch(void* const* d_in, const int* in_sizes, int n_in,
                              void* d_out, int out_size) {
    Ptrs ps;
    for (int i = 0; i < 9; i++) ps.p[i] = (const float*)d_in[i];
    const unsigned* targets = (const unsigned*)d_in[9];
    float* out = (float*)d_out;

    const int N = in_sizes[9];   // 16384 rows
    const int npairs = (N + 1) / 2;

    int sms = 148;
    cudaDeviceGetAttribute(&sms, cudaDevAttrMultiProcessorCount, 0);
    int grid = sms * 5;          // match __launch_bounds__(288, 5)
    if (grid > npairs) grid = npairs;

    margin_softmax_kernel<<<grid, BLOCK>>>(ps, targets, out, N);
}

// round 15
// speedup vs baseline: 1.0735x; 1.0735x over previous
#include <cuda_runtime.h>
#include <cuda_bf16.h>
#include <math_constants.h>

// N=16384 rows, C=1000 classes, 9 matrices (outputs1..8 + mimic).
// Per row/matrix: margin = (x[target] == top1) ? top1 - top2 : 0
// out_threshold = softmax(margins / 2) per row -> d_out[1 + row*9 + m]
// max_preds = max over all elements of matrices 0..7 -> d_out[0]
//
// R12 design (92.7us: row-pair/iter, 9 warps/block = 9 matrices, __ldcs
// payload, double-buffered margins) + DYNAMIC pair scheduling:
//  - global atomic counter hands out pairs; absorbs the ragged tail
//    (8192 pairs over 760 blocks) and per-SM CTA spread
//  - next pair index fetched during compute, double-buffered in shared,
//    published by the existing per-iteration barrier (no extra syncs)
//  - counter reset by last-block finalize -> graph-replay safe
// Payload load structure UNCHANGED from R12 (R13 showed inserting loads
// into the batch breaks LDG batching and costs ~7%).

#define C_DIM  1000
#define CHUNKS 250          // C_DIM / 4 float4 chunks per row
#define BLOCK  288          // 9 warps
#define NEG_INF (-CUDART_INF_F)
#define ENC_NEG_INF 0x007FFFFFu   // enc_f(-inf)

struct Ptrs { const float* p[9]; };

__device__ unsigned g_max_enc = ENC_NEG_INF;
__device__ unsigned g_done    = 0u;
__device__ unsigned g_pair    = 0u;

__device__ __forceinline__ unsigned enc_f(float x) {
    unsigned u = __float_as_uint(x);
    return (u & 0x80000000u) ? ~u : (u | 0x80000000u);
}
__device__ __forceinline__ float dec_f(unsigned e) {
    return (e & 0x80000000u) ? __uint_as_float(e ^ 0x80000000u)
                             : __uint_as_float(~e);
}

// accumulate top-2 of a float4 into (t1, t2)
__device__ __forceinline__ void acc4(float4 v, float& t1, float& t2) {
    float hi1 = fmaxf(v.x, v.y), lo1 = fminf(v.x, v.y);
    float hi2 = fmaxf(v.z, v.w), lo2 = fminf(v.z, v.w);
    float m1 = fmaxf(hi1, hi2);
    float m2 = fmaxf(fminf(hi1, hi2), (hi1 >= hi2) ? lo1 : lo2);
    t2 = fmaxf(fminf(t1, m1), fmaxf(t2, m2));
    t1 = fmaxf(t1, m1);
}

__global__ __launch_bounds__(BLOCK, 5)
void margin_softmax_kernel(Ptrs ptrs, const unsigned* __restrict__ t32,
                           float* __restrict__ out, int nrows) {
    const int t    = threadIdx.x;
    const int lane = t & 31;
    const int w    = t >> 5;          // warp index == matrix index 0..8

    __shared__ float    s_margin[2][2][12]; // [buf][row-in-pair][warp], padded
    __shared__ float    s_gm[8];
    __shared__ unsigned s_next[2];          // double-buffered next pair index

    // targets dtype detect, once: int64 values < 1000 => all odd words 0
    unsigned odd  = __ldg(&t32[2 * lane + 1]);
    unsigned is32 = __reduce_or_sync(0xFFFFFFFFu, odd);

    const float* base = ptrs.p[w];
    float gm = NEG_INF;               // per-warp running max (lane 0 authoritative)

    const unsigned npairs = (unsigned)((nrows + 1) >> 1);

    if (t == 0) s_next[0] = atomicAdd(&g_pair, 1u);
    __syncthreads();

    int it = 0;
    for (;; ++it) {
        const unsigned p = s_next[it & 1];
        if (p >= npairs) break;

        // grab the next pair now; published by this iteration's barrier.
        if (t == 0) s_next[(it + 1) & 1] = atomicAdd(&g_pair, 1u);

        const int row0 = 2 * (int)p;
        const int row1 = row0 + 1;

        long long tg0, tg1;
        if (is32) {
            tg0 = (long long)__ldg(&((const int*)t32)[row0]);
            tg1 = (long long)__ldg(&((const int*)t32)[row1]);
        } else {
            tg0 = __ldg(&((const long long*)t32)[row0]);
            tg1 = __ldg(&((const long long*)t32)[row1]);
        }

        const float* rowp0 = base + (size_t)row0 * C_DIM;
        const float* rowp1 = rowp0 + C_DIM;
        const float4* r0 = reinterpret_cast<const float4*>(rowp0);
        const float4* r1 = reinterpret_cast<const float4*>(rowp1);

        float tv0 = __ldg(&rowp0[tg0]);
        float tv1 = __ldg(&rowp1[tg1]);

        // wave A: both rows, chunks lane + {0,32,64,96} -> 8 loads in flight
        float4 a00 = __ldcs(&r0[lane]);
        float4 a01 = __ldcs(&r0[lane + 32]);
        float4 a02 = __ldcs(&r0[lane + 64]);
        float4 a03 = __ldcs(&r0[lane + 96]);
        float4 a10 = __ldcs(&r1[lane]);
        float4 a11 = __ldcs(&r1[lane + 32]);
        float4 a12 = __ldcs(&r1[lane + 64]);
        float4 a13 = __ldcs(&r1[lane + 96]);

        float t1a = NEG_INF, t2a = NEG_INF;   // row0 top-2
        float t1b = NEG_INF, t2b = NEG_INF;   // row1 top-2
        acc4(a00, t1a, t2a); acc4(a10, t1b, t2b);
        acc4(a01, t1a, t2a); acc4(a11, t1b, t2b);
        acc4(a02, t1a, t2a); acc4(a12, t1b, t2b);
        acc4(a03, t1a, t2a); acc4(a13, t1b, t2b);

        // wave B: both rows, chunks lane + {128,160,192,224} (last predicated)
        float4 nf = make_float4(NEG_INF, NEG_INF, NEG_INF, NEG_INF);
        float4 b00 = __ldcs(&r0[lane + 128]);
        float4 b01 = __ldcs(&r0[lane + 160]);
        float4 b02 = __ldcs(&r0[lane + 192]);
        float4 b03 = (lane + 224 < CHUNKS) ? __ldcs(&r0[lane + 224]) : nf;
        float4 b10 = __ldcs(&r1[lane + 128]);
        float4 b11 = __ldcs(&r1[lane + 160]);
        float4 b12 = __ldcs(&r1[lane + 192]);
        float4 b13 = (lane + 224 < CHUNKS) ? __ldcs(&r1[lane + 224]) : nf;

        acc4(b00, t1a, t2a); acc4(b10, t1b, t2b);
        acc4(b01, t1a, t2a); acc4(b11, t1b, t2b);
        acc4(b02, t1a, t2a); acc4(b12, t1b, t2b);
        acc4(b03, t1a, t2a); acc4(b13, t1b, t2b);

        // warp top-2 reduction, 4 streams in one loop
#pragma unroll
        for (int off = 16; off > 0; off >>= 1) {
            float o1a = __shfl_down_sync(0xFFFFFFFFu, t1a, off);
            float o2a = __shfl_down_sync(0xFFFFFFFFu, t2a, off);
            float o1b = __shfl_down_sync(0xFFFFFFFFu, t1b, off);
            float o2b = __shfl_down_sync(0xFFFFFFFFu, t2b, off);
            t2a = fmaxf(fminf(t1a, o1a), fmaxf(t2a, o2a));
            t1a = fmaxf(t1a, o1a);
            t2b = fmaxf(fminf(t1b, o1b), fmaxf(t2b, o2b));
            t1b = fmaxf(t1b, o1b);
        }
        if (lane == 0) {
            s_margin[it & 1][0][w] = (tv0 == t1a) ? (t1a - t2a) : 0.0f;
            s_margin[it & 1][1][w] = (tv1 == t1b) ? (t1b - t2b) : 0.0f;
            gm = fmaxf(gm, fmaxf(t1a, t1b));    // row max == top1
        }
        __syncthreads();   // publishes s_margin AND s_next[(it+1)&1]

        if (w == 0) {
            // two softmaxes in one warp: lanes 0..8 -> row0, 16..24 -> row1
            int half = lane >> 4;      // 0 or 1
            int l16  = lane & 15;
            float m = (l16 < 9) ? s_margin[it & 1][half][l16] : NEG_INF;
            float mm = m;
#pragma unroll
            for (int off = 8; off > 0; off >>= 1)
                mm = fmaxf(mm, __shfl_xor_sync(0xFFFFFFFFu, mm, off, 16));
            float e = __expf((m - mm) * 0.5f);
            float sum = e;
#pragma unroll
            for (int off = 8; off > 0; off >>= 1)
                sum += __shfl_xor_sync(0xFFFFFFFFu, sum, off, 16);
            int row = row0 + half;
            if (l16 < 9 && row < nrows)
                out[1 + (size_t)row * 9 + l16] = __fdividef(e, sum);
        }
        // s_margin/s_next WAR across iterations protected by double buffering.
    }

    // block-level scalar max: one shared write per warp, one atomic per block
    if (lane == 0 && w < 8) s_gm[w] = gm;
    __syncthreads();
    if (t == 0) {
        float g = s_gm[0];
#pragma unroll
        for (int i = 1; i < 8; i++) g = fmaxf(g, s_gm[i]);
        atomicMax(&g_max_enc, enc_f(g));
        __threadfence();
        unsigned done = atomicAdd(&g_done, 1u);
        if (done == gridDim.x - 1) {
            __threadfence();
            unsigned cur = atomicOr(&g_max_enc, 0u);   // atomic read
            out[0] = dec_f(cur);
            // reset scratch for next graph replay (all g_pair fetches done:
            // every block's last fetch precedes its g_done arrival)
            g_max_enc = ENC_NEG_INF;
            g_done    = 0u;
            g_pair    = 0u;
        }
    }
}

extern "C" void kernel_launch(void* const* d_in, const int* in_sizes, int n_in,
                              void* d_out, int out_size) {
    Ptrs ps;
    for (int i = 0; i < 9; i++) ps.p[i] = (const float*)d_in[i];
    const unsigned* targets = (const unsigned*)d_in[9];
    float* out = (float*)d_out;

    const int N = in_sizes[9];   // 16384 rows
    const int npairs = (N + 1) / 2;

    int sms = 148;
    cudaDeviceGetAttribute(&sms, cudaDevAttrMultiProcessorCount, 0);
    int grid = sms * 5;          // match __launch_bounds__(288, 5)
    if (grid > npairs) grid = npairs;

    margin_softmax_kernel<<<grid, BLOCK>>>(ps, targets, out, N);
}